// round 14
// baseline (speedup 1.0000x reference)
#include <cuda_runtime.h>
#include <cstdint>

#define SEQ    512
#define BATCH  512
#define IN_DIM 128
#define NQ     8
#define D_TOT  136   // IN_DIM + NQ

// Scratch: Zx[s][b][o], o = g*8 + q
__device__ float g_zx[(size_t)SEQ * BATCH * 32];

typedef unsigned long long ull;

// --- packed fp32x2 ops (zx kernel only) ---
__device__ __forceinline__ ull fma2(ull a, ull b, ull c) {
    ull d; asm("fma.rn.f32x2 %0, %1, %2, %3;" : "=l"(d) : "l"(a), "l"(b), "l"(c)); return d;
}
__device__ __forceinline__ ull pack2(float lo, float hi) {
    ull d; asm("mov.b64 %0, {%1, %2};" : "=l"(d) : "r"(__float_as_uint(lo)), "r"(__float_as_uint(hi))); return d;
}
__device__ __forceinline__ void unpack2(ull v, float& lo, float& hi) {
    unsigned a, b; asm("mov.b64 {%0, %1}, %2;" : "=r"(a), "=r"(b) : "l"(v));
    lo = __uint_as_float(a); hi = __uint_as_float(b);
}
__device__ __forceinline__ ull dup2(float x) {
    ull d; unsigned u = __float_as_uint(x);
    asm("mov.b64 %0, {%1, %1};" : "=l"(d) : "r"(u)); return d;
}
__device__ __forceinline__ float rcp_fast(float x) {
    float r; asm("rcp.approx.f32 %0, %1;" : "=f"(r) : "f"(x)); return r;
}

// ============================================================================
// Kernel 1: Zx[row][o] = sum_d x[row][d] * W[o][d] + b[o] + qp[o]
//   (unchanged from round 13)
// ============================================================================
#define ZX_ROWS 256
#define XPAD    258
#define ZPAD    130

__global__ __launch_bounds__(128) void zx_kernel(
    const float* __restrict__ x, const float* __restrict__ W,
    const float* __restrict__ b, const float* __restrict__ qp)
{
    __shared__ ulonglong2 Ws[IN_DIM * 4];
    __shared__ ulonglong2 Ws_hi[IN_DIM * 4];
    __shared__ ull bias2[16];
    __shared__ float xs[4352];

    int tid = threadIdx.x;

    for (int i = tid; i < 1088; i += 128)
        ((float4*)xs)[i] = ((const float4*)W)[i];
    if (tid < 16) bias2[tid] = pack2(b[2 * tid] + qp[2 * tid],
                                     b[2 * tid + 1] + qp[2 * tid + 1]);
    __syncthreads();

    float* WsF   = (float*)Ws;
    float* WsFhi = (float*)Ws_hi;
    for (int i = tid; i < IN_DIM * 32; i += 128) {
        int d = i >> 5, o = i & 31;
        float w = xs[o * D_TOT + d];
        if (o < 16) WsF[d * 16 + o] = w;
        else        WsFhi[d * 16 + (o - 16)] = w;
    }

    int rowbase = blockIdx.x * ZX_ROWS;
    const float* xblk = x + (size_t)rowbase * IN_DIM;

    ull acc0[16], acc1[16];
#pragma unroll
    for (int i = 0; i < 16; i++) { acc0[i] = bias2[i]; acc1[i] = bias2[i]; }

    for (int t = 0; t < IN_DIM / 16; t++) {
        __syncthreads();
#pragma unroll
        for (int it = 0; it < 8; it++) {
            int idx = it * 128 + tid;
            int r = idx >> 2, dq = idx & 3;
            float4 v = *(const float4*)(xblk + (size_t)r * IN_DIM + t * 16 + dq * 4);
            xs[(dq * 4 + 0) * XPAD + r] = v.x;
            xs[(dq * 4 + 1) * XPAD + r] = v.y;
            xs[(dq * 4 + 2) * XPAD + r] = v.z;
            xs[(dq * 4 + 3) * XPAD + r] = v.w;
        }
        __syncthreads();

#pragma unroll
        for (int dd = 0; dd < 16; dd++) {
            int d = t * 16 + dd;
            ull xa = dup2(xs[dd * XPAD + tid]);
            ull xb = dup2(xs[dd * XPAD + tid + 128]);
            const ulonglong2* wlo = Ws    + d * 4;
            const ulonglong2* whi = Ws_hi + d * 4;
#pragma unroll
            for (int j = 0; j < 4; j++) {
                ulonglong2 wp = wlo[j];
                acc0[2 * j]     = fma2(xa, wp.x, acc0[2 * j]);
                acc0[2 * j + 1] = fma2(xa, wp.y, acc0[2 * j + 1]);
                acc1[2 * j]     = fma2(xb, wp.x, acc1[2 * j]);
                acc1[2 * j + 1] = fma2(xb, wp.y, acc1[2 * j + 1]);
            }
#pragma unroll
            for (int j = 0; j < 4; j++) {
                ulonglong2 wp = whi[j];
                acc0[8 + 2 * j]     = fma2(xa, wp.x, acc0[8 + 2 * j]);
                acc0[8 + 2 * j + 1] = fma2(xa, wp.y, acc0[8 + 2 * j + 1]);
                acc1[8 + 2 * j]     = fma2(xb, wp.x, acc1[8 + 2 * j]);
                acc1[8 + 2 * j + 1] = fma2(xb, wp.y, acc1[8 + 2 * j + 1]);
            }
        }
    }

#pragma unroll
    for (int h = 0; h < 2; h++) {
        __syncthreads();
        const ull* ac = h ? acc1 : acc0;
#pragma unroll
        for (int j = 0; j < 16; j++) {
            float lo, hi; unpack2(ac[j], lo, hi);
            xs[(2 * j) * ZPAD + tid]     = lo;
            xs[(2 * j + 1) * ZPAD + tid] = hi;
        }
        __syncthreads();
        int rb = rowbase + h * 128;
#pragma unroll
        for (int k = 0; k < 8; k++) {
            int idx = k * 128 + tid;
            int r = idx >> 3, d4 = idx & 7;
            float4 v = make_float4(xs[(4 * d4 + 0) * ZPAD + r],
                                   xs[(4 * d4 + 1) * ZPAD + r],
                                   xs[(4 * d4 + 2) * ZPAD + r],
                                   xs[(4 * d4 + 3) * ZPAD + r]);
            *(float4*)(g_zx + (size_t)(rb + r) * 32 + d4 * 4) = v;
        }
    }
}

// ============================================================================
// Kernel 2: recurrence. 16 LANES PER BATCH: lane = bl*16 + g*4 + sub.
//   FULL SCALAR math (no pack/unpack movs on the chain).
//   All exchanges via parallel shuffles: 3 (cumprod) + 8 (gates) + 8 (h).
// ============================================================================
__global__ void __launch_bounds__(32, 1) rnn_kernel(
    const float* __restrict__ W, const float* __restrict__ h0,
    const float* __restrict__ c0, float* __restrict__ out)
{
    const unsigned FULL = 0xffffffffu;
    int lane = threadIdx.x;
    int sub = lane & 3;                  // q-pair index (q = 2sub, 2sub+1)
    int g   = (lane >> 2) & 3;           // gate
    int bl  = lane >> 4;                 // batch within warp 0..1
    int b   = blockIdx.x * 2 + bl;       // batch 0..511
    int xbase = (lane & 16) | sub;       // gate-exchange source base lane

    // Wh[r][j]: W row (g*8 + 2*sub + r), col 128+j — scalar
    float Wh[2][8];
#pragma unroll
    for (int r = 0; r < 2; r++) {
        const float* wr = W + (g * 8 + 2 * sub + r) * D_TOT + IN_DIM;
#pragma unroll
        for (int j = 0; j < 8; j++) Wh[r][j] = wr[j];
    }

    float h[8];
#pragma unroll
    for (int j = 0; j < 8; j++) h[j] = h0[b * 8 + j];

    float cA = c0[b * 8 + 2 * sub];
    float cB = c0[b * 8 + 2 * sub + 1];

    // per-lane gate rational coefficients (arg/output scale folded in)
    bool is_g = (g == 2);
    const float P0 = is_g ? 105.0f : 26.25f;
    const float P1 = is_g ? 10.0f  : 0.625f;
    const float Q1 = is_g ? 45.0f  : 11.25f;
    const float Q2 = is_g ? 1.0f   : 0.0625f;
    const float OB = is_g ? 0.0f   : 0.5f;
    // loop-invariant cumprod predicates
    bool p1 = (sub >= 1), p2 = (sub >= 2), p3 = (sub >= 3);

    const float2* zp = (const float2*)g_zx + ((size_t)b * 16 + (lane & 15));
    const size_t Z2STRIDE = (size_t)BATCH * 16;

    float2 zb[4];
#pragma unroll
    for (int u = 0; u < 4; u++) zb[u] = zp[(size_t)u * Z2STRIDE];
    const float2* pf = zp + 4 * Z2STRIDE;

    float2* op2 = (float2*)out + ((size_t)b * 4 + sub);
    const size_t O2STRIDE = (size_t)BATCH * 4;

    float hA = 0.0f, hB = 0.0f;

    auto step = [&](float2 zc) {
        // dot: 2 rows, each as two parallel 4-chains
        float u0 = fmaf(h[0], Wh[0][0], zc.x);
        float v0 = h[4] * Wh[0][4];
        float u1 = fmaf(h[0], Wh[1][0], zc.y);
        float v1 = h[4] * Wh[1][4];
#pragma unroll
        for (int j = 1; j < 4; j++) {
            u0 = fmaf(h[j],     Wh[0][j],     u0);
            v0 = fmaf(h[j + 4], Wh[0][j + 4], v0);
            u1 = fmaf(h[j],     Wh[1][j],     u1);
            v1 = fmaf(h[j + 4], Wh[1][j + 4], v1);
        }
        float a0 = __cosf(u0 + v0);
        float a1 = __cosf(u1 + v1);

        // cumprod prefix: pair product + 3 parallel width-4 shuffles
        float k1 = a0 * a1;
        float t0 = __shfl_sync(FULL, k1, 0, 4);
        float t1 = __shfl_sync(FULL, k1, 1, 4);
        float t2 = __shfl_sync(FULL, k1, 2, 4);
        float s1 = p1 ? t0 : 1.0f;
        float s2 = p2 ? t1 : 1.0f;
        float s3 = p3 ? t2 : 1.0f;
        float m = s1 * (s2 * s3);
        float X0 = m * a0;
        float X1 = m * k1;

        // gate rational: v = OB + x(P0 + P1 t)/(105 + Q1 t + Q2 t^2), pair rcp
        float T0 = X0 * X0, T1 = X1 * X1;
        float N0 = X0 * fmaf(P1, T0, P0);
        float N1 = X1 * fmaf(P1, T1, P0);
        float D0 = fmaf(fmaf(Q2, T0, Q1), T0, 105.0f);
        float D1 = fmaf(fmaf(Q2, T1, Q1), T1, 105.0f);
        float inv = rcp_fast(D0 * D1);
        float V0 = fmaf(N0 * D1, inv, OB);
        float V1 = fmaf(N1 * D0, inv, OB);

        // gate exchange: 8 parallel idx-shuffles (no smem, no barrier)
        float f0 = __shfl_sync(FULL, V0, xbase);
        float f1 = __shfl_sync(FULL, V1, xbase);
        float i0 = __shfl_sync(FULL, V0, xbase + 4);
        float i1 = __shfl_sync(FULL, V1, xbase + 4);
        float g0 = __shfl_sync(FULL, V0, xbase + 8);
        float g1 = __shfl_sync(FULL, V1, xbase + 8);
        float o0 = __shfl_sync(FULL, V0, xbase + 12);
        float o1 = __shfl_sync(FULL, V1, xbase + 12);

        // cell update + cell tanh (Pade [5/4], pair rcp)
        cA = fmaf(f0, cA, i0 * g0);
        cB = fmaf(f1, cB, i1 * g1);
        float TA = cA * cA, TB = cB * cB;
        float NA = cA * fmaf(TA + 105.0f, TA, 945.0f);
        float NB = cB * fmaf(TB + 105.0f, TB, 945.0f);
        float DA = fmaf(fmaf(15.0f, TA, 420.0f), TA, 945.0f);
        float DB = fmaf(fmaf(15.0f, TB, 420.0f), TB, 945.0f);
        float iv = rcp_fast(DA * DB);
        hA = o0 * ((NA * DB) * iv);
        hB = o1 * ((NB * DA) * iv);

        // h gather: 8 parallel width-4 shuffles
#pragma unroll
        for (int k = 0; k < 4; k++) {
            h[2 * k]     = __shfl_sync(FULL, hA, k, 4);
            h[2 * k + 1] = __shfl_sync(FULL, hB, k, 4);
        }

        // unconditional store (4 gate lanes: identical value, same address)
        *op2 = make_float2(hA, hB);
        op2 += O2STRIDE;
    };

    // main loop: steps 0..507, prefetch 4..511 — clamp-free ptr increment
    for (int s = 0; s <= SEQ - 8; s += 4) {
#pragma unroll
        for (int u = 0; u < 4; u++) {
            float2 zn = *pf; pf += Z2STRIDE;
            step(zb[u]);
            zb[u] = zn;
        }
    }
    // peeled final 4 steps
#pragma unroll
    for (int u = 0; u < 4; u++)
        step(zb[u]);

    // Final states: h_f then c_f (unconditional, redundant identical writes)
    size_t base2 = (size_t)SEQ * BATCH * 4;          // float2 units
    ((float2*)out)[base2 + (size_t)b * 4 + sub] = make_float2(hA, hB);
    ((float2*)out)[base2 + BATCH * 4 + (size_t)b * 4 + sub] = make_float2(cA, cB);
}

extern "C" void kernel_launch(void* const* d_in, const int* in_sizes, int n_in,
                              void* d_out, int out_size) {
    const float* x  = (const float*)d_in[0];   // inputs (512,512,128)
    const float* h0 = (const float*)d_in[1];   // (512,8)
    const float* c0 = (const float*)d_in[2];   // (512,8)
    const float* W  = (const float*)d_in[3];   // (4,8,136)
    const float* b  = (const float*)d_in[4];   // (4,8)
    const float* qp = (const float*)d_in[5];   // (4,8)
    float* out = (float*)d_out;

    zx_kernel<<<(SEQ * BATCH) / ZX_ROWS, 128>>>(x, W, b, qp);
    rnn_kernel<<<BATCH / 2, 32>>>(W, h0, c0, out);
}

// round 15
// speedup vs baseline: 1.0895x; 1.0895x over previous
#include <cuda_runtime.h>
#include <cstdint>

#define SEQ    512
#define BATCH  512
#define IN_DIM 128
#define NQ     8
#define D_TOT  136   // IN_DIM + NQ

// Scratch: Zx[s][b][o], o = g*8 + q
__device__ float g_zx[(size_t)SEQ * BATCH * 32];

typedef unsigned long long ull;

// --- packed fp32x2 ops (zx kernel only) ---
__device__ __forceinline__ ull fma2(ull a, ull b, ull c) {
    ull d; asm("fma.rn.f32x2 %0, %1, %2, %3;" : "=l"(d) : "l"(a), "l"(b), "l"(c)); return d;
}
__device__ __forceinline__ ull pack2(float lo, float hi) {
    ull d; asm("mov.b64 %0, {%1, %2};" : "=l"(d) : "r"(__float_as_uint(lo)), "r"(__float_as_uint(hi))); return d;
}
__device__ __forceinline__ void unpack2(ull v, float& lo, float& hi) {
    unsigned a, b; asm("mov.b64 {%0, %1}, %2;" : "=r"(a), "=r"(b) : "l"(v));
    lo = __uint_as_float(a); hi = __uint_as_float(b);
}
__device__ __forceinline__ ull dup2(float x) {
    ull d; unsigned u = __float_as_uint(x);
    asm("mov.b64 %0, {%1, %1};" : "=l"(d) : "r"(u)); return d;
}
// hardware tanh (MUFU.TANH, sm_75+)
__device__ __forceinline__ float tanh_hw(float x) {
    float r; asm("tanh.approx.f32 %0, %1;" : "=f"(r) : "f"(x)); return r;
}

// ============================================================================
// Kernel 1: Zx[row][o] = sum_d x[row][d] * W[o][d] + b[o] + qp[o]
//   (unchanged from round 13/14)
// ============================================================================
#define ZX_ROWS 256
#define XPAD    258
#define ZPAD    130

__global__ __launch_bounds__(128) void zx_kernel(
    const float* __restrict__ x, const float* __restrict__ W,
    const float* __restrict__ b, const float* __restrict__ qp)
{
    __shared__ ulonglong2 Ws[IN_DIM * 4];
    __shared__ ulonglong2 Ws_hi[IN_DIM * 4];
    __shared__ ull bias2[16];
    __shared__ float xs[4352];

    int tid = threadIdx.x;

    for (int i = tid; i < 1088; i += 128)
        ((float4*)xs)[i] = ((const float4*)W)[i];
    if (tid < 16) bias2[tid] = pack2(b[2 * tid] + qp[2 * tid],
                                     b[2 * tid + 1] + qp[2 * tid + 1]);
    __syncthreads();

    float* WsF   = (float*)Ws;
    float* WsFhi = (float*)Ws_hi;
    for (int i = tid; i < IN_DIM * 32; i += 128) {
        int d = i >> 5, o = i & 31;
        float w = xs[o * D_TOT + d];
        if (o < 16) WsF[d * 16 + o] = w;
        else        WsFhi[d * 16 + (o - 16)] = w;
    }

    int rowbase = blockIdx.x * ZX_ROWS;
    const float* xblk = x + (size_t)rowbase * IN_DIM;

    ull acc0[16], acc1[16];
#pragma unroll
    for (int i = 0; i < 16; i++) { acc0[i] = bias2[i]; acc1[i] = bias2[i]; }

    for (int t = 0; t < IN_DIM / 16; t++) {
        __syncthreads();
#pragma unroll
        for (int it = 0; it < 8; it++) {
            int idx = it * 128 + tid;
            int r = idx >> 2, dq = idx & 3;
            float4 v = *(const float4*)(xblk + (size_t)r * IN_DIM + t * 16 + dq * 4);
            xs[(dq * 4 + 0) * XPAD + r] = v.x;
            xs[(dq * 4 + 1) * XPAD + r] = v.y;
            xs[(dq * 4 + 2) * XPAD + r] = v.z;
            xs[(dq * 4 + 3) * XPAD + r] = v.w;
        }
        __syncthreads();

#pragma unroll
        for (int dd = 0; dd < 16; dd++) {
            int d = t * 16 + dd;
            ull xa = dup2(xs[dd * XPAD + tid]);
            ull xb = dup2(xs[dd * XPAD + tid + 128]);
            const ulonglong2* wlo = Ws    + d * 4;
            const ulonglong2* whi = Ws_hi + d * 4;
#pragma unroll
            for (int j = 0; j < 4; j++) {
                ulonglong2 wp = wlo[j];
                acc0[2 * j]     = fma2(xa, wp.x, acc0[2 * j]);
                acc0[2 * j + 1] = fma2(xa, wp.y, acc0[2 * j + 1]);
                acc1[2 * j]     = fma2(xb, wp.x, acc1[2 * j]);
                acc1[2 * j + 1] = fma2(xb, wp.y, acc1[2 * j + 1]);
            }
#pragma unroll
            for (int j = 0; j < 4; j++) {
                ulonglong2 wp = whi[j];
                acc0[8 + 2 * j]     = fma2(xa, wp.x, acc0[8 + 2 * j]);
                acc0[8 + 2 * j + 1] = fma2(xa, wp.y, acc0[8 + 2 * j + 1]);
                acc1[8 + 2 * j]     = fma2(xb, wp.x, acc1[8 + 2 * j]);
                acc1[8 + 2 * j + 1] = fma2(xb, wp.y, acc1[8 + 2 * j + 1]);
            }
        }
    }

#pragma unroll
    for (int h = 0; h < 2; h++) {
        __syncthreads();
        const ull* ac = h ? acc1 : acc0;
#pragma unroll
        for (int j = 0; j < 16; j++) {
            float lo, hi; unpack2(ac[j], lo, hi);
            xs[(2 * j) * ZPAD + tid]     = lo;
            xs[(2 * j + 1) * ZPAD + tid] = hi;
        }
        __syncthreads();
        int rb = rowbase + h * 128;
#pragma unroll
        for (int k = 0; k < 8; k++) {
            int idx = k * 128 + tid;
            int r = idx >> 3, d4 = idx & 7;
            float4 v = make_float4(xs[(4 * d4 + 0) * ZPAD + r],
                                   xs[(4 * d4 + 1) * ZPAD + r],
                                   xs[(4 * d4 + 2) * ZPAD + r],
                                   xs[(4 * d4 + 3) * ZPAD + r]);
            *(float4*)(g_zx + (size_t)(rb + r) * 32 + d4 * 4) = v;
        }
    }
}

// ============================================================================
// Kernel 2: recurrence. 16 LANES PER BATCH: lane = bl*16 + g*4 + sub.
//   Full scalar; all exchanges via parallel shuffles; HW tanh.approx for
//   both gate activations and cell tanh (kills both RCP rational chains).
// ============================================================================
__global__ void __launch_bounds__(32, 1) rnn_kernel(
    const float* __restrict__ W, const float* __restrict__ h0,
    const float* __restrict__ c0, float* __restrict__ out)
{
    const unsigned FULL = 0xffffffffu;
    int lane = threadIdx.x;
    int sub = lane & 3;                  // q-pair index (q = 2sub, 2sub+1)
    int g   = (lane >> 2) & 3;           // gate
    int bl  = lane >> 4;                 // batch within warp 0..1
    int b   = blockIdx.x * 2 + bl;       // batch 0..511
    int xbase = (lane & 16) | sub;       // gate-exchange source base lane

    // Wh[r][j]: W row (g*8 + 2*sub + r), col 128+j — scalar
    float Wh[2][8];
#pragma unroll
    for (int r = 0; r < 2; r++) {
        const float* wr = W + (g * 8 + 2 * sub + r) * D_TOT + IN_DIM;
#pragma unroll
        for (int j = 0; j < 8; j++) Wh[r][j] = wr[j];
    }

    float h[8];
#pragma unroll
    for (int j = 0; j < 8; j++) h[j] = h0[b * 8 + j];

    float cA = c0[b * 8 + 2 * sub];
    float cB = c0[b * 8 + 2 * sub + 1];

    // gate: sigmoid(x) = 0.5 + 0.5*tanh(x/2)  (f,i,o lanes: ASC=0.5, OB=0.5)
    //       g-gate:    tanh(x)                (ASC=1,   OB=0)
    bool is_g = (g == 2);
    const float ASC = is_g ? 1.0f : 0.5f;
    const float OB  = is_g ? 0.0f : 0.5f;
    // loop-invariant cumprod predicates
    bool p1 = (sub >= 1), p2 = (sub >= 2), p3 = (sub >= 3);

    const float2* zp = (const float2*)g_zx + ((size_t)b * 16 + (lane & 15));
    const size_t Z2STRIDE = (size_t)BATCH * 16;

    float2 zb[4];
#pragma unroll
    for (int u = 0; u < 4; u++) zb[u] = zp[(size_t)u * Z2STRIDE];
    const float2* pf = zp + 4 * Z2STRIDE;

    float2* op2 = (float2*)out + ((size_t)b * 4 + sub);
    const size_t O2STRIDE = (size_t)BATCH * 4;

    float hA = 0.0f, hB = 0.0f;

    auto step = [&](float2 zc) {
        // dot: 2 rows, each as two parallel 4-chains
        float u0 = fmaf(h[0], Wh[0][0], zc.x);
        float v0 = h[4] * Wh[0][4];
        float u1 = fmaf(h[0], Wh[1][0], zc.y);
        float v1 = h[4] * Wh[1][4];
#pragma unroll
        for (int j = 1; j < 4; j++) {
            u0 = fmaf(h[j],     Wh[0][j],     u0);
            v0 = fmaf(h[j + 4], Wh[0][j + 4], v0);
            u1 = fmaf(h[j],     Wh[1][j],     u1);
            v1 = fmaf(h[j + 4], Wh[1][j + 4], v1);
        }
        float a0 = __cosf(u0 + v0);
        float a1 = __cosf(u1 + v1);

        // cumprod prefix: pair product + 3 parallel width-4 shuffles
        float k1 = a0 * a1;
        // pre-scale own pair (off the prefix chain)
        float am0 = ASC * a0;
        float am1 = ASC * k1;
        float t0 = __shfl_sync(FULL, k1, 0, 4);
        float t1 = __shfl_sync(FULL, k1, 1, 4);
        float t2 = __shfl_sync(FULL, k1, 2, 4);
        float s1 = p1 ? t0 : 1.0f;
        float s2 = p2 ? t1 : 1.0f;
        float s3 = p3 ? t2 : 1.0f;
        float m = s1 * (s2 * s3);

        // gate activation via HW tanh: V = OB + ASC * tanh(ASC * prod)
        float V0 = fmaf(ASC, tanh_hw(m * am0), OB);
        float V1 = fmaf(ASC, tanh_hw(m * am1), OB);

        // gate exchange: 8 parallel idx-shuffles (no smem, no barrier)
        float f0 = __shfl_sync(FULL, V0, xbase);
        float f1 = __shfl_sync(FULL, V1, xbase);
        float i0 = __shfl_sync(FULL, V0, xbase + 4);
        float i1 = __shfl_sync(FULL, V1, xbase + 4);
        float g0 = __shfl_sync(FULL, V0, xbase + 8);
        float g1 = __shfl_sync(FULL, V1, xbase + 8);
        float o0 = __shfl_sync(FULL, V0, xbase + 12);
        float o1 = __shfl_sync(FULL, V1, xbase + 12);

        // cell update + HW cell tanh
        cA = fmaf(f0, cA, i0 * g0);
        cB = fmaf(f1, cB, i1 * g1);
        hA = o0 * tanh_hw(cA);
        hB = o1 * tanh_hw(cB);

        // h gather: 8 parallel width-4 shuffles
#pragma unroll
        for (int k = 0; k < 4; k++) {
            h[2 * k]     = __shfl_sync(FULL, hA, k, 4);
            h[2 * k + 1] = __shfl_sync(FULL, hB, k, 4);
        }

        // unconditional store (4 gate lanes: identical value, same address)
        *op2 = make_float2(hA, hB);
        op2 += O2STRIDE;
    };

    // main loop: steps 0..507, prefetch 4..511 — clamp-free ptr increment
    for (int s = 0; s <= SEQ - 8; s += 4) {
#pragma unroll
        for (int u = 0; u < 4; u++) {
            float2 zn = *pf; pf += Z2STRIDE;
            step(zb[u]);
            zb[u] = zn;
        }
    }
    // peeled final 4 steps
#pragma unroll
    for (int u = 0; u < 4; u++)
        step(zb[u]);

    // Final states: h_f then c_f (unconditional, redundant identical writes)
    size_t base2 = (size_t)SEQ * BATCH * 4;          // float2 units
    ((float2*)out)[base2 + (size_t)b * 4 + sub] = make_float2(hA, hB);
    ((float2*)out)[base2 + BATCH * 4 + (size_t)b * 4 + sub] = make_float2(cA, cB);
}

extern "C" void kernel_launch(void* const* d_in, const int* in_sizes, int n_in,
                              void* d_out, int out_size) {
    const float* x  = (const float*)d_in[0];   // inputs (512,512,128)
    const float* h0 = (const float*)d_in[1];   // (512,8)
    const float* c0 = (const float*)d_in[2];   // (512,8)
    const float* W  = (const float*)d_in[3];   // (4,8,136)
    const float* b  = (const float*)d_in[4];   // (4,8)
    const float* qp = (const float*)d_in[5];   // (4,8)
    float* out = (float*)d_out;

    zx_kernel<<<(SEQ * BATCH) / ZX_ROWS, 128>>>(x, W, b, qp);
    rnn_kernel<<<BATCH / 2, 32>>>(W, h0, c0, out);
}

// round 16
// speedup vs baseline: 1.1236x; 1.0313x over previous
#include <cuda_runtime.h>
#include <cstdint>

#define SEQ    512
#define BATCH  512
#define IN_DIM 128
#define NQ     8
#define D_TOT  136   // IN_DIM + NQ

// Scratch: Zx[s][b][o], o = g*8 + q
__device__ float g_zx[(size_t)SEQ * BATCH * 32];

typedef unsigned long long ull;

// --- packed fp32x2 ops (zx kernel only) ---
__device__ __forceinline__ ull fma2(ull a, ull b, ull c) {
    ull d; asm("fma.rn.f32x2 %0, %1, %2, %3;" : "=l"(d) : "l"(a), "l"(b), "l"(c)); return d;
}
__device__ __forceinline__ ull pack2(float lo, float hi) {
    ull d; asm("mov.b64 %0, {%1, %2};" : "=l"(d) : "r"(__float_as_uint(lo)), "r"(__float_as_uint(hi))); return d;
}
__device__ __forceinline__ void unpack2(ull v, float& lo, float& hi) {
    unsigned a, b; asm("mov.b64 {%0, %1}, %2;" : "=r"(a), "=r"(b) : "l"(v));
    lo = __uint_as_float(a); hi = __uint_as_float(b);
}
__device__ __forceinline__ ull dup2(float x) {
    ull d; unsigned u = __float_as_uint(x);
    asm("mov.b64 %0, {%1, %1};" : "=l"(d) : "r"(u)); return d;
}
// hardware tanh (MUFU.TANH)
__device__ __forceinline__ float tanh_hw(float x) {
    float r; asm("tanh.approx.f32 %0, %1;" : "=f"(r) : "f"(x)); return r;
}

// ============================================================================
// Kernel 1: Zx[row][o] = sum_d x[row][d] * W[o][d] + b[o] + qp[o]
//   Round-13 structure + REGISTER DOUBLE-BUFFERED x staging (tile t+1's LDGs
//   issue before tile t's compute, hiding per-tile DRAM latency).
// ============================================================================
#define ZX_ROWS 256
#define XPAD    258
#define ZPAD    130
#define NT      (IN_DIM / 16)   // 8 tiles

__global__ __launch_bounds__(128) void zx_kernel(
    const float* __restrict__ x, const float* __restrict__ W,
    const float* __restrict__ b, const float* __restrict__ qp)
{
    __shared__ ulonglong2 Ws[IN_DIM * 4];
    __shared__ ulonglong2 Ws_hi[IN_DIM * 4];
    __shared__ ull bias2[16];
    __shared__ float xs[4352];

    int tid = threadIdx.x;

    for (int i = tid; i < 1088; i += 128)
        ((float4*)xs)[i] = ((const float4*)W)[i];
    if (tid < 16) bias2[tid] = pack2(b[2 * tid] + qp[2 * tid],
                                     b[2 * tid + 1] + qp[2 * tid + 1]);
    __syncthreads();

    float* WsF   = (float*)Ws;
    float* WsFhi = (float*)Ws_hi;
    for (int i = tid; i < IN_DIM * 32; i += 128) {
        int d = i >> 5, o = i & 31;
        float w = xs[o * D_TOT + d];
        if (o < 16) WsF[d * 16 + o] = w;
        else        WsFhi[d * 16 + (o - 16)] = w;
    }

    int rowbase = blockIdx.x * ZX_ROWS;
    const float* xblk = x + (size_t)rowbase * IN_DIM;

    // per-thread staging coords
    int sr = tid >> 2, sdq = tid & 3;

    ull acc0[16], acc1[16];
#pragma unroll
    for (int i = 0; i < 16; i++) { acc0[i] = bias2[i]; acc1[i] = bias2[i]; }

    // preload tile 0 into registers
    float4 xreg[8];
#pragma unroll
    for (int it = 0; it < 8; it++) {
        int r = sr + it * 32;
        xreg[it] = *(const float4*)(xblk + (size_t)r * IN_DIM + sdq * 4);
    }

    for (int t = 0; t < NT; t++) {
        __syncthreads();   // xs free (W scatter read at t=0 / prev compute)
        // scatter regs -> transposed xs
#pragma unroll
        for (int it = 0; it < 8; it++) {
            int r = sr + it * 32;
            float4 v = xreg[it];
            xs[(sdq * 4 + 0) * XPAD + r] = v.x;
            xs[(sdq * 4 + 1) * XPAD + r] = v.y;
            xs[(sdq * 4 + 2) * XPAD + r] = v.z;
            xs[(sdq * 4 + 3) * XPAD + r] = v.w;
        }
        __syncthreads();

        // issue next tile's loads (latency hidden under compute below)
        if (t + 1 < NT) {
#pragma unroll
            for (int it = 0; it < 8; it++) {
                int r = sr + it * 32;
                xreg[it] = *(const float4*)(xblk + (size_t)r * IN_DIM +
                                            (t + 1) * 16 + sdq * 4);
            }
        }

#pragma unroll
        for (int dd = 0; dd < 16; dd++) {
            int d = t * 16 + dd;
            ull xa = dup2(xs[dd * XPAD + tid]);
            ull xb = dup2(xs[dd * XPAD + tid + 128]);
            const ulonglong2* wlo = Ws    + d * 4;
            const ulonglong2* whi = Ws_hi + d * 4;
#pragma unroll
            for (int j = 0; j < 4; j++) {
                ulonglong2 wp = wlo[j];
                acc0[2 * j]     = fma2(xa, wp.x, acc0[2 * j]);
                acc0[2 * j + 1] = fma2(xa, wp.y, acc0[2 * j + 1]);
                acc1[2 * j]     = fma2(xb, wp.x, acc1[2 * j]);
                acc1[2 * j + 1] = fma2(xb, wp.y, acc1[2 * j + 1]);
            }
#pragma unroll
            for (int j = 0; j < 4; j++) {
                ulonglong2 wp = whi[j];
                acc0[8 + 2 * j]     = fma2(xa, wp.x, acc0[8 + 2 * j]);
                acc0[8 + 2 * j + 1] = fma2(xa, wp.y, acc0[8 + 2 * j + 1]);
                acc1[8 + 2 * j]     = fma2(xb, wp.x, acc1[8 + 2 * j]);
                acc1[8 + 2 * j + 1] = fma2(xb, wp.y, acc1[8 + 2 * j + 1]);
            }
        }
    }

    // output: stage transposed, store coalesced (2 halves)
#pragma unroll
    for (int h = 0; h < 2; h++) {
        __syncthreads();
        const ull* ac = h ? acc1 : acc0;
#pragma unroll
        for (int j = 0; j < 16; j++) {
            float lo, hi; unpack2(ac[j], lo, hi);
            xs[(2 * j) * ZPAD + tid]     = lo;
            xs[(2 * j + 1) * ZPAD + tid] = hi;
        }
        __syncthreads();
        int rb = rowbase + h * 128;
#pragma unroll
        for (int k = 0; k < 8; k++) {
            int idx = k * 128 + tid;
            int r = idx >> 3, d4 = idx & 7;
            float4 v = make_float4(xs[(4 * d4 + 0) * ZPAD + r],
                                   xs[(4 * d4 + 1) * ZPAD + r],
                                   xs[(4 * d4 + 2) * ZPAD + r],
                                   xs[(4 * d4 + 3) * ZPAD + r]);
            *(float4*)(g_zx + (size_t)(rb + r) * 32 + d4 * 4) = v;
        }
    }
}

// ============================================================================
// Kernel 2: recurrence. 32 LANES PER BATCH: lane = g*8 + q (one q per lane).
//   3 MUFU/step/lane (1 cos + 2 tanh). Cumprod = all-gather (8 parallel
//   width-8 shfl) + sel + tree. Gate exchange = 4 full-width idx-shfl.
//   h-gather = 8 width-8 shfl. Branch-free; redundant identical stores.
// ============================================================================
__global__ void __launch_bounds__(128, 1) rnn_kernel(
    const float* __restrict__ W, const float* __restrict__ h0,
    const float* __restrict__ c0, float* __restrict__ out)
{
    const unsigned FULL = 0xffffffffu;
    int lane = threadIdx.x & 31;
    int warp = threadIdx.x >> 5;
    int q = lane & 7;
    int g = lane >> 3;
    int b = blockIdx.x * 4 + warp;       // batch 0..511

    // Wh[j]: W row (g*8+q), col 128+j
    float Wh[8];
    {
        const float* wr = W + lane * D_TOT + IN_DIM;
#pragma unroll
        for (int j = 0; j < 8; j++) Wh[j] = wr[j];
    }

    float h[8];
#pragma unroll
    for (int j = 0; j < 8; j++) h[j] = h0[b * 8 + j];
    float c = c0[b * 8 + q];             // replicated across gate groups

    bool is_g = (g == 2);
    const float ASC = is_g ? 1.0f : 0.5f;
    const float OB  = is_g ? 0.0f : 0.5f;

    // loop-invariant cumprod keep-predicates (j <= q)
    bool p0 = (q >= 0), p1 = (q >= 1), p2 = (q >= 2), p3 = (q >= 3);
    bool p4 = (q >= 4), p5 = (q >= 5), p6 = (q >= 6), p7 = (q >= 7);
    (void)p0;

    const float* zp = g_zx + ((size_t)b * 32 + lane);
    const int ZSTRIDE = BATCH * 32;

    float zb[4];
#pragma unroll
    for (int u = 0; u < 4; u++) zb[u] = zp[(size_t)u * ZSTRIDE];
    const float* pf = zp + 4 * (size_t)ZSTRIDE;

    float* op = out + ((size_t)b * 8 + q);
    const size_t OSTRIDE = (size_t)BATCH * 8;

    float hq = 0.0f;

    auto step = [&](float zc) {
        // dot: two parallel 4-chains
        float u0 = fmaf(h[0], Wh[0], zc);
        float v0 = h[4] * Wh[4];
#pragma unroll
        for (int j = 1; j < 4; j++) {
            u0 = fmaf(h[j],     Wh[j],     u0);
            v0 = fmaf(h[j + 4], Wh[j + 4], v0);
        }
        float a = __cosf(u0 + v0);

        // cumprod over q (within gate group): all-gather + masked tree
        float c0v = __shfl_sync(FULL, a, 0, 8);
        float c1v = __shfl_sync(FULL, a, 1, 8);
        float c2v = __shfl_sync(FULL, a, 2, 8);
        float c3v = __shfl_sync(FULL, a, 3, 8);
        float c4v = __shfl_sync(FULL, a, 4, 8);
        float c5v = __shfl_sync(FULL, a, 5, 8);
        float c6v = __shfl_sync(FULL, a, 6, 8);
        float c7v = __shfl_sync(FULL, a, 7, 8);
        c1v = p1 ? c1v : 1.0f;
        c2v = p2 ? c2v : 1.0f;
        c3v = p3 ? c3v : 1.0f;
        c4v = p4 ? c4v : 1.0f;
        c5v = p5 ? c5v : 1.0f;
        c6v = p6 ? c6v : 1.0f;
        c7v = p7 ? c7v : 1.0f;
        float m01 = c0v * c1v, m23 = c2v * c3v;
        float m45 = c4v * c5v, m67 = c6v * c7v;
        float prod = (m01 * m23) * (m45 * m67);

        // gate value: V = OB + ASC * tanh(ASC * prod)
        float V = fmaf(ASC, tanh_hw(ASC * prod), OB);

        // gate exchange: 4 full-width idx-shuffles
        float fv = __shfl_sync(FULL, V, q);
        float iv = __shfl_sync(FULL, V, 8 + q);
        float gv = __shfl_sync(FULL, V, 16 + q);
        float ov = __shfl_sync(FULL, V, 24 + q);

        // cell update + HW cell tanh
        c = fmaf(fv, c, iv * gv);
        hq = ov * tanh_hw(c);

        // h gather: 8 parallel width-8 shuffles
#pragma unroll
        for (int j = 0; j < 8; j++)
            h[j] = __shfl_sync(FULL, hq, j, 8);

        // unconditional store (4 gate groups: identical value, same address)
        *op = hq;
        op += OSTRIDE;
    };

    // main loop: steps 0..507, prefetch 4..511 — clamp-free ptr increment
    for (int s = 0; s <= SEQ - 8; s += 4) {
#pragma unroll
        for (int u = 0; u < 4; u++) {
            float zn = *pf; pf += ZSTRIDE;
            step(zb[u]);
            zb[u] = zn;
        }
    }
    // peeled final 4 steps
#pragma unroll
    for (int u = 0; u < 4; u++)
        step(zb[u]);

    // Final states: h_f then c_f (unconditional, redundant identical writes)
    size_t base = (size_t)SEQ * BATCH * 8;
    out[base + (size_t)b * 8 + q]             = hq;
    out[base + BATCH * 8 + (size_t)b * 8 + q] = c;
}

extern "C" void kernel_launch(void* const* d_in, const int* in_sizes, int n_in,
                              void* d_out, int out_size) {
    const float* x  = (const float*)d_in[0];   // inputs (512,512,128)
    const float* h0 = (const float*)d_in[1];   // (512,8)
    const float* c0 = (const float*)d_in[2];   // (512,8)
    const float* W  = (const float*)d_in[3];   // (4,8,136)
    const float* b  = (const float*)d_in[4];   // (4,8)
    const float* qp = (const float*)d_in[5];   // (4,8)
    float* out = (float*)d_out;

    zx_kernel<<<(SEQ * BATCH) / ZX_ROWS, 128>>>(x, W, b, qp);
    rnn_kernel<<<BATCH / 4, 128>>>(W, h0, c0, out);
}